// round 8
// baseline (speedup 1.0000x reference)
#include <cuda_runtime.h>
#include <cstdint>
#include <cstddef>

#define T_STEPS 2048
#define BATCH   512
#define HID     33
#define G4      132
#define ODIM    18
#define H1DIM   72
#define XSTRIDE (BATCH * G4)   // per-t stride in xg (floats)

// Static device scratch (allocation-free).
// xg: [T][B][33 units][4 gates] preactivations (biases absorbed), reused per layer.
// y:  [T][B][33] layer output, reused.
__device__ float g_xg[(size_t)T_STEPS * BATCH * G4];
__device__ float g_y [(size_t)T_STEPS * BATCH * HID];

typedef unsigned long long u64;

__device__ __forceinline__ void fma2(u64 &acc, u64 a, u64 b) {
    asm("fma.rn.f32x2 %0, %1, %2, %0;" : "+l"(acc) : "l"(a), "l"(b));
}
__device__ __forceinline__ u64 pack2(float lo, float hi) {
    u64 r; asm("mov.b64 %0, {%1,%2};" : "=l"(r) : "f"(lo), "f"(hi)); return r;
}
__device__ __forceinline__ float2 unpack2(u64 v) {
    float2 r; asm("mov.b64 {%0,%1}, %2;" : "=f"(r.x), "=f"(r.y) : "l"(v)); return r;
}
__device__ __forceinline__ float sigm_(float x) {
    return __fdividef(1.f, 1.f + __expf(-x));
}
__device__ __forceinline__ float tanh_(float x) {
    float e = __expf(2.f * x);
    return 1.f - __fdividef(2.f, e + 1.f);
}

// ---------------------------------------------------------------------------
// xg precompute: xg[t][b][u][gb] = Wih[gb*33+u]·x_t(b) + b_ih + b_hh
// (gate-interleaved output so the rec warp reads one float4 per lane).
// One block = one t, 16 consecutive b. Thread j owns W row j.
// ---------------------------------------------------------------------------
template<int IN, bool XBF>
__global__ __launch_bounds__(G4)
void xg_kernel(const float* __restrict__ xin,
               const float* __restrict__ Wih,
               const float* __restrict__ bih,
               const float* __restrict__ bhh)
{
    constexpr int NP  = (IN + 1) / 2 + (((IN + 1) / 2) & 1);  // 6 / 18 pairs
    constexpr int INP = 2 * NP;
    const int t  = blockIdx.y;
    const int b0 = blockIdx.x * 16;
    const int j  = threadIdx.x;
    const int u  = j % 33;
    const int gb = j / 33;

    __shared__ __align__(16) float x_sh[16][INP];

    for (int i = j; i < 16 * INP; i += G4) (&x_sh[0][0])[i] = 0.f;
    __syncthreads();
    if (XBF) {
        for (int i = j; i < 16 * IN; i += G4)
            x_sh[i / IN][i % IN] = xin[((size_t)(b0 + i / IN) * T_STEPS + t) * IN + (i % IN)];
    } else {
        const float* src = g_y + ((size_t)t * BATCH + b0) * HID;
        for (int i = j; i < 16 * HID; i += G4)
            x_sh[i / HID][i % HID] = src[i];
    }
    __syncthreads();

    u64 w2[NP];
#pragma unroll
    for (int p = 0; p < NP; p++) {
        int m = 2 * p;
        float lo = (m     < IN) ? Wih[j * IN + m]     : 0.f;
        float hi = (m + 1 < IN) ? Wih[j * IN + m + 1] : 0.f;
        w2[p] = pack2(lo, hi);
    }
    const float bias = bih[j] + bhh[j];

    float* outp = g_xg + ((size_t)t * BATCH + b0) * G4 + u * 4 + gb;
#pragma unroll 4
    for (int g = 0; g < 16; g++) {
        u64 a0 = 0ull, a1 = 0ull;
        const ulonglong2* xv = (const ulonglong2*)x_sh[g];
#pragma unroll
        for (int q = 0; q < NP / 2; q++) {
            ulonglong2 v = xv[q];
            fma2(a0, w2[2 * q],     v.x);
            fma2(a1, w2[2 * q + 1], v.y);
        }
        float2 u0 = unpack2(a0), u1 = unpack2(a1);
        outp[(size_t)g * G4] = (u0.x + u0.y) + (u1.x + u1.y) + bias;
    }
}

// ---------------------------------------------------------------------------
// Recurrence: ONE WARP per batch element, no __syncthreads in the loop.
// Lane l owns unit l: 4 register-resident weight rows (i,f,g,o), plus a 5th
// shared-memory row chain covering unit 32 (lanes 0..3 produce i/f/g/o_32,
// broadcast by shuffle, c_32 updated uniformly by all lanes).
// CTA = 4 warps (4 elements) so warps map to distinct SMSPs. grid=128 <= SMs.
// ---------------------------------------------------------------------------
template<int YDST>
__global__ __launch_bounds__(128, 1)
void rec_kernel(const float* __restrict__ Whh, float* __restrict__ hid)
{
    const int tid  = threadIdx.x;
    const int e    = tid >> 5;          // warp within CTA
    const int lane = tid & 31;
    const int b    = blockIdx.x * 4 + e;

    __shared__ __align__(16) float h_sh[4][2][36];
    __shared__ __align__(16) u64   w5_sh[4][18];     // unit-32 rows (i,f,g,o)

    // init shared: h buffers zero (incl. pad), w5 rows
    for (int i = tid; i < 4 * 2 * 36; i += 128) (&h_sh[0][0][0])[i] = 0.f;
    if (tid < 68) {
        int rk = tid / 17, p = tid % 17;
        int row = rk * 33 + 32;
        float lo = Whh[row * HID + 2 * p];
        float hi = (2 * p + 1 < HID) ? Whh[row * HID + 2 * p + 1] : 0.f;
        w5_sh[rk][p] = pack2(lo, hi);
    }
    if (tid >= 68 && tid < 72) w5_sh[tid - 68][17] = 0ull;
    __syncthreads();

    // own-unit weights, f32x2-packed over k (17 pairs = 34 slots, slot33=0)
    u64 w0[17], w1[17], w2[17], w3[17];
#pragma unroll
    for (int p = 0; p < 17; p++) {
        int m = 2 * p;
        float h1_ = (m + 1 < HID) ? 1.f : 0.f;
        w0[p] = pack2(Whh[(0 * 33 + lane) * HID + m], h1_ * Whh[(0 * 33 + lane) * HID + ((m + 1 < HID) ? m + 1 : 0)]);
        w1[p] = pack2(Whh[(1 * 33 + lane) * HID + m], h1_ * Whh[(1 * 33 + lane) * HID + ((m + 1 < HID) ? m + 1 : 0)]);
        w2[p] = pack2(Whh[(2 * 33 + lane) * HID + m], h1_ * Whh[(2 * 33 + lane) * HID + ((m + 1 < HID) ? m + 1 : 0)]);
        w3[p] = pack2(Whh[(3 * 33 + lane) * HID + m], h1_ * Whh[(3 * 33 + lane) * HID + ((m + 1 < HID) ? m + 1 : 0)]);
    }

    const int l4 = (lane < 3) ? lane : 3;
    const ulonglong2* w5v = (const ulonglong2*)w5_sh[l4];
    const u64 w5t = w5_sh[l4][16];
    // lane 2 computes g_32: tanh(x) = 2*sigm(2x) - 1
    const float S5 = (lane == 2) ? 2.f : 1.f;
    const float A5 = (lane == 2) ? 2.f : 1.f;
    const float B5 = (lane == 2) ? -1.f : 0.f;

    // xg ring (depth 4): one float4 (own gates) + one float (unit-32 row l4)
    const float*  xgb  = g_xg + (size_t)b * G4;
    const float4* xg4p = (const float4*)(xgb) + lane;          // + t*XSTRIDE/4
    const float*  xg5p = xgb + 128 + l4;                       // + t*XSTRIDE
    float4 r0 = xg4p[0], r1 = xg4p[(size_t)XSTRIDE / 4],
           r2 = xg4p[2 * (size_t)XSTRIDE / 4], r3 = xg4p[3 * (size_t)XSTRIDE / 4];
    float  s0 = xg5p[0], s1 = xg5p[(size_t)XSTRIDE],
           s2 = xg5p[2 * (size_t)XSTRIDE], s3 = xg5p[3 * (size_t)XSTRIDE];

    float c = 0.f, c5 = 0.f;

    for (int t = 0; t < T_STEPS; ++t) {
        const int pc = t & 1, pn = pc ^ 1;

        float4 xg4 = r0; float xg5 = s0;
        r0 = r1; r1 = r2; r2 = r3;
        s0 = s1; s1 = s2; s2 = s3;
        if (t + 4 < T_STEPS) {
            r3 = __ldg(xg4p + (size_t)(t + 4) * (XSTRIDE / 4));
            s3 = __ldg(xg5p + (size_t)(t + 4) * XSTRIDE);
        }

        // five 17-deep f32x2 chains over h (broadcast LDS)
        u64 a0 = 0ull, a1 = 0ull, a2 = 0ull, a3 = 0ull, a4 = 0ull;
        const ulonglong2* hv = (const ulonglong2*)h_sh[e][pc];
#pragma unroll
        for (int q = 0; q < 8; q++) {
            ulonglong2 v = hv[q];
            fma2(a0, w0[2 * q], v.x); fma2(a0, w0[2 * q + 1], v.y);
            fma2(a1, w1[2 * q], v.x); fma2(a1, w1[2 * q + 1], v.y);
            fma2(a2, w2[2 * q], v.x); fma2(a2, w2[2 * q + 1], v.y);
            fma2(a3, w3[2 * q], v.x); fma2(a3, w3[2 * q + 1], v.y);
            ulonglong2 wq = w5v[q];
            fma2(a4, wq.x, v.x);      fma2(a4, wq.y, v.y);
        }
        u64 vt = ((const u64*)h_sh[e][pc])[16];   // (h32, 0)
        fma2(a0, w0[16], vt); fma2(a1, w1[16], vt);
        fma2(a2, w2[16], vt); fma2(a3, w3[16], vt);
        fma2(a4, w5t, vt);

        float2 f0 = unpack2(a0), f1 = unpack2(a1), f2 = unpack2(a2),
               f3 = unpack2(a3), f4 = unpack2(a4);
        float pi = f0.x + f0.y + xg4.x;
        float pf = f1.x + f1.y + xg4.y;
        float pg = f2.x + f2.y + xg4.z;
        float po = f3.x + f3.y + xg4.w;
        float p5 = f4.x + f4.y + xg5;

        float gi = sigm_(pi);
        float gf = sigm_(pf);
        float gg = tanh_(pg);
        float go = sigm_(po);
        float g5 = A5 * sigm_(S5 * p5) + B5;   // i/f/o_32: sigm; g_32: tanh

        // unit-32 gates broadcast (uniform in all lanes)
        float i32 = __shfl_sync(0xFFFFFFFFu, g5, 0);
        float f32 = __shfl_sync(0xFFFFFFFFu, g5, 1);
        float g32 = __shfl_sync(0xFFFFFFFFu, g5, 2);
        float o32 = __shfl_sync(0xFFFFFFFFu, g5, 3);

        c  = gf * c + gi * gg;
        c5 = f32 * c5 + i32 * g32;
        float h  = go  * tanh_(c);
        float h5 = o32 * tanh_(c5);

        h_sh[e][pn][lane] = h;
        if (lane == 0) h_sh[e][pn][32] = h5;

        if (YDST) {
            float* yp = g_y + ((size_t)t * BATCH + b) * HID;
            yp[lane] = h;
            if (lane == 0) yp[32] = h5;
        }
        if (t == T_STEPS - 1) {
            hid[b * HID + lane] = h;
            if (lane == 0) hid[b * HID + 32] = h5;
        }
        __syncwarp();
    }
}

// ---------------------------------------------------------------------------
// MLP head: out = GELU(hid@W1^T + b1) @ W2^T + b2
// ---------------------------------------------------------------------------
__global__ __launch_bounds__(H1DIM)
void head_kernel(const float* __restrict__ hid,
                 const float* __restrict__ W1, const float* __restrict__ b1,
                 const float* __restrict__ W2, const float* __restrict__ b2,
                 float* __restrict__ out)
{
    const int rr = blockIdx.x;
    const int u  = threadIdx.x;
    __shared__ float hrow[HID];
    __shared__ float h1[H1DIM];

    if (u < HID) hrow[u] = hid[rr * HID + u];
    __syncthreads();

    float s = b1[u];
#pragma unroll
    for (int m = 0; m < HID; m++) s += W1[u * HID + m] * hrow[m];
    h1[u] = 0.5f * s * (1.f + erff(s * 0.70710678118654752f));  // exact GELU
    __syncthreads();

    if (u < ODIM) {
        float s2 = b2[u];
#pragma unroll
        for (int m = 0; m < H1DIM; m++) s2 += W2[u * H1DIM + m] * h1[m];
        out[rr * ODIM + u] = s2;
    }
}

extern "C" void kernel_launch(void* const* d_in, const int* in_sizes, int n_in,
                              void* d_out, int out_size)
{
    const float* x    = (const float*)d_in[0];
    const float* Wih0 = (const float*)d_in[1];
    const float* Whh0 = (const float*)d_in[2];
    const float* bih0 = (const float*)d_in[3];
    const float* bhh0 = (const float*)d_in[4];
    const float* Wih1 = (const float*)d_in[5];
    const float* Whh1 = (const float*)d_in[6];
    const float* bih1 = (const float*)d_in[7];
    const float* bhh1 = (const float*)d_in[8];
    const float* Wih2 = (const float*)d_in[9];
    const float* Whh2 = (const float*)d_in[10];
    const float* bih2 = (const float*)d_in[11];
    const float* bhh2 = (const float*)d_in[12];
    const float* W1   = (const float*)d_in[13];
    const float* b1   = (const float*)d_in[14];
    const float* W2   = (const float*)d_in[15];
    const float* b2   = (const float*)d_in[16];

    float* out = (float*)d_out;                      // [3, 512, 18]
    float* hid = out + 3 * BATCH * ODIM;             // [3, 512, 33]

    dim3 ggrid(BATCH / 16, T_STEPS);

    xg_kernel<11, true ><<<ggrid, G4>>>(x, Wih0, bih0, bhh0);
    rec_kernel<1><<<BATCH / 4, 128>>>(Whh0, hid);
    xg_kernel<33, false><<<ggrid, G4>>>(nullptr, Wih1, bih1, bhh1);
    rec_kernel<1><<<BATCH / 4, 128>>>(Whh1, hid + BATCH * HID);
    xg_kernel<33, false><<<ggrid, G4>>>(nullptr, Wih2, bih2, bhh2);
    rec_kernel<0><<<BATCH / 4, 128>>>(Whh2, hid + 2 * BATCH * HID);
    head_kernel<<<3 * BATCH, H1DIM>>>(hid, W1, b1, W2, b2, out);
}

// round 9
// speedup vs baseline: 1.5020x; 1.5020x over previous
#include <cuda_runtime.h>
#include <cstdint>
#include <cstddef>

#define T_STEPS 2048
#define BATCH   512
#define HID     33
#define G4      132
#define ODIM    18
#define H1DIM   72
#define CS      128                 // steps per chunk
#define NCHUNK  (T_STEPS / CS)      // 16
#define NWAVE   (NCHUNK + 2)        // 18 pipelined waves

// Static device scratch (allocation-free).
__device__ float g_y0[(size_t)T_STEPS * BATCH * HID];   // layer0 output
__device__ float g_y1[(size_t)T_STEPS * BATCH * HID];   // layer1 output
__device__ float g_h[3][BATCH][HID];                    // persisted h per layer
__device__ float g_c[3][BATCH][HID];                    // persisted c per layer

typedef unsigned long long u64;

__device__ __forceinline__ void fma2(u64 &acc, u64 a, u64 b) {
    asm("fma.rn.f32x2 %0, %1, %2, %0;" : "+l"(acc) : "l"(a), "l"(b));
}
__device__ __forceinline__ u64 pack2(float lo, float hi) {
    u64 r; asm("mov.b64 %0, {%1,%2};" : "=l"(r) : "f"(lo), "f"(hi)); return r;
}
__device__ __forceinline__ float2 unpack2(u64 v) {
    float2 r; asm("mov.b64 {%0,%1}, %2;" : "=f"(r.x), "=f"(r.y) : "l"(v)); return r;
}
__device__ __forceinline__ float sigm_(float x) {
    return __fdividef(1.f, 1.f + __expf(-x));
}
__device__ __forceinline__ float tanh_(float x) {
    float e = __expf(2.f * x);
    return 1.f - __fdividef(2.f, e + 1.f);
}

// ---------------------------------------------------------------------------
// One chunk (CS steps) of one layer's recurrence for one batch element.
// Identical step structure to the proven R5 kernel (132 threads, gate j per
// thread, register-resident f32x2 weights, double-buffered h, 2 barriers).
// h,c persisted in g_h/g_c between chunk launches; x prefetch clamped to the
// chunk so it never reads the producer layer's not-yet-written steps.
// ---------------------------------------------------------------------------
template<int IN, bool XBF, bool YW>
__device__ __forceinline__ void run_chunk(
    int b, int j, int chunk,
    const float* __restrict__ xp,
    const float* __restrict__ Wih, const float* __restrict__ Whh,
    const float* __restrict__ bih, const float* __restrict__ bhh,
    float* __restrict__ yp, float* __restrict__ hrow, float* __restrict__ crow,
    float* __restrict__ hid,
    float (*h_sh)[36], float* x_sh, float* g_sh)
{
    constexpr int INP = ((IN + 3) / 4) * 4;   // 12 / 36
    constexpr int NPI = INP / 2;
    const int t0 = chunk * CS;

    // pack weights (f32x2 over k) — amortized over CS steps
    u64 whh2[18];
#pragma unroll
    for (int p = 0; p < 18; p++) {
        int m = 2 * p;
        float lo = (m     < HID) ? Whh[j * HID + m]     : 0.f;
        float hi = (m + 1 < HID) ? Whh[j * HID + m + 1] : 0.f;
        whh2[p] = pack2(lo, hi);
    }
    u64 wih2[NPI];
#pragma unroll
    for (int p = 0; p < NPI; p++) {
        int m = 2 * p;
        float lo = (m     < IN) ? Wih[j * IN + m]     : 0.f;
        float hi = (m + 1 < IN) ? Wih[j * IN + m + 1] : 0.f;
        wih2[p] = pack2(lo, hi);
    }
    const float bias = bih[j] + bhh[j];
    const bool is_g  = (j >= 66 && j < 99);        // gate order i,f,g,o
    const bool ldr   = (j >= 64) && (j < 64 + IN); // x loader threads
    const int  li    = j - 64;

    auto xval = [&](int t, int i) -> float {
        if (XBF) return xp[((size_t)b * T_STEPS + t) * IN + i];
        else     return xp[((size_t)t * BATCH + b) * HID + i];
    };

    // chunk-entry state
    if (j < 36) { h_sh[0][j] = 0.f; h_sh[1][j] = 0.f; }
    if (j >= IN && j < INP) x_sh[j] = 0.f;
    if (chunk > 0 && j < HID) h_sh[0][j] = hrow[j];
    if (ldr) x_sh[li] = xval(t0, li);
    __syncthreads();

    float c  = (chunk > 0 && j < HID) ? crow[j] : 0.f;
    float hl = 0.f;
    float xr = ldr ? xval(t0 + 1, li) : 0.f;   // x(t+1) entering step t

    for (int s = 0; s < CS; ++s) {
        const int t  = t0 + s;
        const int pc = s & 1, pn = pc ^ 1;

        // depth-2 x prefetch, clamped to this chunk (producer may not have
        // written beyond it yet)
        float xr2 = 0.f;
        if (ldr && (s + 2) < CS) xr2 = xval(t + 2, li);

        // gate pre-activation: two independent f32x2 chains
        u64 acch = 0ull, accx = 0ull;
        const ulonglong2* hv = (const ulonglong2*)h_sh[pc];
        const ulonglong2* xv = (const ulonglong2*)x_sh;
#pragma unroll
        for (int q = 0; q < 9; q++) {
            ulonglong2 v = hv[q];                 // LDS.128 broadcast
            fma2(acch, whh2[2 * q],     v.x);
            fma2(acch, whh2[2 * q + 1], v.y);
        }
#pragma unroll
        for (int q = 0; q < INP / 4; q++) {
            ulonglong2 v = xv[q];
            fma2(accx, wih2[2 * q],     v.x);
            fma2(accx, wih2[2 * q + 1], v.y);
        }
        float2 ah = unpack2(acch), ax = unpack2(accx);
        float pre = (ah.x + ah.y) + (ax.x + ax.y) + bias;
        g_sh[j] = is_g ? tanh_(pre) : sigm_(pre);
        __syncthreads();                          // gates visible

        if (j < HID) {
            float gi = g_sh[j];
            float gf = g_sh[j + 33];
            float gg = g_sh[j + 66];
            float go = g_sh[j + 99];
            c  = gf * c + gi * gg;
            hl = go * tanh_(c);
            h_sh[pn][j] = hl;
            if (YW) yp[((size_t)t * BATCH + b) * HID + j] = hl;
            if (t == T_STEPS - 1) hid[b * HID + j] = hl;
        } else if (ldr) {
            x_sh[li] = xr;                        // publish x(t+1)
            xr = xr2;
        }
        __syncthreads();                          // h_t visible
    }

    // persist state for the next chunk launch
    if (j < HID) { hrow[j] = hl; crow[j] = c; }
}

// ---------------------------------------------------------------------------
// One pipeline wave: CTA (b, layer) runs chunk = wave - layer (if valid).
// Steady-state waves have 1536 active CTAs -> ~2-3x the warp overlap of the
// single-layer launches. Inter-launch ordering provides the y0/y1 fences.
// ---------------------------------------------------------------------------
__global__ __launch_bounds__(G4)
void wave_kernel(int wave, const float* __restrict__ x,
                 const float* __restrict__ Wih0, const float* __restrict__ Whh0,
                 const float* __restrict__ bih0, const float* __restrict__ bhh0,
                 const float* __restrict__ Wih1, const float* __restrict__ Whh1,
                 const float* __restrict__ bih1, const float* __restrict__ bhh1,
                 const float* __restrict__ Wih2, const float* __restrict__ Whh2,
                 const float* __restrict__ bih2, const float* __restrict__ bhh2,
                 float* __restrict__ hid)
{
    const int b     = blockIdx.x;
    const int layer = blockIdx.y;
    const int chunk = wave - layer;
    if (chunk < 0 || chunk >= NCHUNK) return;

    __shared__ __align__(16) float h_sh[2][36];
    __shared__ __align__(16) float x_sh[36];
    __shared__ float g_sh[G4];
    const int j = threadIdx.x;

    if (layer == 0)
        run_chunk<11, true,  true >(b, j, chunk, x,    Wih0, Whh0, bih0, bhh0,
                                    g_y0, g_h[0][b], g_c[0][b],
                                    hid,                  h_sh, x_sh, g_sh);
    else if (layer == 1)
        run_chunk<33, false, true >(b, j, chunk, g_y0, Wih1, Whh1, bih1, bhh1,
                                    g_y1, g_h[1][b], g_c[1][b],
                                    hid + BATCH * HID,    h_sh, x_sh, g_sh);
    else
        run_chunk<33, false, false>(b, j, chunk, g_y1, Wih2, Whh2, bih2, bhh2,
                                    nullptr, g_h[2][b], g_c[2][b],
                                    hid + 2 * BATCH * HID, h_sh, x_sh, g_sh);
}

// ---------------------------------------------------------------------------
// MLP head: out = GELU(hid@W1^T + b1) @ W2^T + b2
// ---------------------------------------------------------------------------
__global__ __launch_bounds__(H1DIM)
void head_kernel(const float* __restrict__ hid,
                 const float* __restrict__ W1, const float* __restrict__ b1,
                 const float* __restrict__ W2, const float* __restrict__ b2,
                 float* __restrict__ out)
{
    const int rr = blockIdx.x;
    const int u  = threadIdx.x;
    __shared__ float hrow[HID];
    __shared__ float h1[H1DIM];

    if (u < HID) hrow[u] = hid[rr * HID + u];
    __syncthreads();

    float s = b1[u];
#pragma unroll
    for (int m = 0; m < HID; m++) s += W1[u * HID + m] * hrow[m];
    h1[u] = 0.5f * s * (1.f + erff(s * 0.70710678118654752f));  // exact GELU
    __syncthreads();

    if (u < ODIM) {
        float s2 = b2[u];
#pragma unroll
        for (int m = 0; m < H1DIM; m++) s2 += W2[u * H1DIM + m] * h1[m];
        out[rr * ODIM + u] = s2;
    }
}

extern "C" void kernel_launch(void* const* d_in, const int* in_sizes, int n_in,
                              void* d_out, int out_size)
{
    const float* x    = (const float*)d_in[0];
    const float* Wih0 = (const float*)d_in[1];
    const float* Whh0 = (const float*)d_in[2];
    const float* bih0 = (const float*)d_in[3];
    const float* bhh0 = (const float*)d_in[4];
    const float* Wih1 = (const float*)d_in[5];
    const float* Whh1 = (const float*)d_in[6];
    const float* bih1 = (const float*)d_in[7];
    const float* bhh1 = (const float*)d_in[8];
    const float* Wih2 = (const float*)d_in[9];
    const float* Whh2 = (const float*)d_in[10];
    const float* bih2 = (const float*)d_in[11];
    const float* bhh2 = (const float*)d_in[12];
    const float* W1   = (const float*)d_in[13];
    const float* b1   = (const float*)d_in[14];
    const float* W2   = (const float*)d_in[15];
    const float* b2   = (const float*)d_in[16];

    float* out = (float*)d_out;                      // [3, 512, 18]
    float* hid = out + 3 * BATCH * ODIM;             // [3, 512, 33]

    dim3 wgrid(BATCH, 3);
    for (int w = 0; w < NWAVE; ++w) {
        wave_kernel<<<wgrid, G4>>>(w, x,
                                   Wih0, Whh0, bih0, bhh0,
                                   Wih1, Whh1, bih1, bhh1,
                                   Wih2, Whh2, bih2, bhh2, hid);
    }
    head_kernel<<<3 * BATCH, H1DIM>>>(hid, W1, b1, W2, b2, out);
}